// round 1
// baseline (speedup 1.0000x reference)
#include <cuda_runtime.h>

// Sparsemax, one CTA per row.
// Exact algorithm: tau >= rowmax - 1 always, so the support is contained in
// C = { x > rowmax - 1 }. Gather C (tiny for Gaussian rows) into smem, solve
// exactly with Newton/Michelot on C, then emit max(x - tau, 0) from registers.

#define THREADS 512
#define VPT     16                 // elements per thread = 8192 / 512
#define NWARP   (THREADS / 32)
#define CAP     1024               // candidate buffer (|C| ~ 6 in practice)
#define COLS    8192

__global__ __launch_bounds__(THREADS)
void sparsemax_kernel(const float* __restrict__ x, float* __restrict__ out, int cols)
{
    __shared__ float s_red[2 * NWARP];
    __shared__ float s_cand[CAP];
    __shared__ int   s_cnt;
    __shared__ float s_tau;
    __shared__ int   s_done;

    const int tid  = threadIdx.x;
    const int lane = tid & 31;
    const int wid  = tid >> 5;
    const long long row = blockIdx.x;

    const float4* xin = reinterpret_cast<const float4*>(x + row * (long long)cols);
    float4* yout      = reinterpret_cast<float4*>(out + row * (long long)cols);

    // ---- load 16 elements/thread into registers (coalesced float4) ----
    float4 v[4];
#pragma unroll
    for (int i = 0; i < 4; ++i) v[i] = xin[tid + i * THREADS];

    if (tid == 0) s_cnt = 0;

    // ---- row max (block reduce) ----
    float m = -3.402823466e38f;
#pragma unroll
    for (int i = 0; i < 4; ++i) {
        m = fmaxf(m, fmaxf(fmaxf(v[i].x, v[i].y), fmaxf(v[i].z, v[i].w)));
    }
#pragma unroll
    for (int o = 16; o > 0; o >>= 1) m = fmaxf(m, __shfl_xor_sync(0xffffffffu, m, o));
    if (lane == 0) s_red[wid] = m;
    __syncthreads();
    if (wid == 0) {
        float t = (lane < NWARP) ? s_red[lane] : -3.402823466e38f;
#pragma unroll
        for (int o = 8; o > 0; o >>= 1) t = fmaxf(t, __shfl_xor_sync(0xffffffffu, t, o));
        if (lane == 0) s_red[0] = t;
    }
    __syncthreads();
    const float rmax   = s_red[0];
    const float thresh = rmax - 1.0f;   // tau >= thresh, support in {x > thresh}

    // ---- gather candidates > thresh into smem ----
#pragma unroll
    for (int i = 0; i < 4; ++i) {
        const float e[4] = {v[i].x, v[i].y, v[i].z, v[i].w};
#pragma unroll
        for (int j = 0; j < 4; ++j) {
            if (e[j] > thresh) {
                int p = atomicAdd(&s_cnt, 1);
                if (p < CAP) s_cand[p] = e[j];
            }
        }
    }
    __syncthreads();
    const int cnt = s_cnt;

    float tau;
    if (cnt <= CAP) {
        // ---- exact Newton/Michelot on candidate set (warp 0) ----
        if (wid == 0) {
            float t0 = thresh;
            for (int it = 0; it < 64; ++it) {
                float s = 0.0f, k = 0.0f;
                for (int i = lane; i < cnt; i += 32) {
                    float c = s_cand[i];
                    if (c > t0) { s += c; k += 1.0f; }
                }
#pragma unroll
                for (int o = 16; o > 0; o >>= 1) {
                    s += __shfl_xor_sync(0xffffffffu, s, o);
                    k += __shfl_xor_sync(0xffffffffu, k, o);
                }
                if (k < 0.5f) break;             // safety (cannot happen in theory)
                float nt = (s - 1.0f) / k;
                if (nt == t0) break;             // exact fixed point reached
                t0 = nt;
            }
            if (lane == 0) s_tau = t0;
        }
        __syncthreads();
        tau = s_tau;
    } else {
        // ---- fallback: block-wide Michelot over full row (never expected) ----
        float t0 = thresh;
        for (int it = 0; it < 64; ++it) {
            float s = 0.0f, k = 0.0f;
#pragma unroll
            for (int i = 0; i < 4; ++i) {
                const float e[4] = {v[i].x, v[i].y, v[i].z, v[i].w};
#pragma unroll
                for (int j = 0; j < 4; ++j) {
                    if (e[j] > t0) { s += e[j]; k += 1.0f; }
                }
            }
#pragma unroll
            for (int o = 16; o > 0; o >>= 1) {
                s += __shfl_xor_sync(0xffffffffu, s, o);
                k += __shfl_xor_sync(0xffffffffu, k, o);
            }
            if (lane == 0) { s_red[2 * wid] = s; s_red[2 * wid + 1] = k; }
            __syncthreads();
            if (tid == 0) {
                float S = 0.0f, K = 0.0f;
                for (int w = 0; w < NWARP; ++w) { S += s_red[2 * w]; K += s_red[2 * w + 1]; }
                float nt = (K < 0.5f) ? t0 : (S - 1.0f) / K;
                s_done = (nt == t0) || (K < 0.5f);
                s_tau  = nt;
            }
            __syncthreads();
            t0 = s_tau;
            if (s_done) break;
        }
        tau = t0;
    }

    // ---- emit output from registers ----
#pragma unroll
    for (int i = 0; i < 4; ++i) {
        float4 r;
        r.x = fmaxf(v[i].x - tau, 0.0f);
        r.y = fmaxf(v[i].y - tau, 0.0f);
        r.z = fmaxf(v[i].z - tau, 0.0f);
        r.w = fmaxf(v[i].w - tau, 0.0f);
        yout[tid + i * THREADS] = r;
    }
}

extern "C" void kernel_launch(void* const* d_in, const int* in_sizes, int n_in,
                              void* d_out, int out_size)
{
    const float* x = (const float*)d_in[0];
    float* out     = (float*)d_out;
    const int rows = in_sizes[0] / COLS;
    sparsemax_kernel<<<rows, THREADS>>>(x, out, COLS);
}

// round 2
// speedup vs baseline: 1.0618x; 1.0618x over previous
#include <cuda_runtime.h>
#include <cstdint>

// Sparsemax, persistent CTAs with TMA (cp.async.bulk) double-buffered rows.
// Exact algorithm: tau >= rowmax - 1, so the support is contained in
// C = { x > rowmax - 1 } (tiny for Gaussian rows). Gather C into smem, solve
// exactly with Newton/Michelot iteration, emit max(x - tau, 0).
// While row r is being reduced/solved/stored, the bulk-copy for row r+stride
// is already in flight into the other smem buffer -> DRAM stays busy.

#define THREADS 512
#define NWARP   16
#define COLS    8192
#define ROW_BYTES (COLS * 4)
#define CAP     512
#define GRID    296        // 2 CTAs per SM x 148 SMs

struct __align__(128) Smem {
    float buf[2][COLS];            // 2 x 32 KB row buffers
    unsigned long long mbar[2];    // full barriers, one per stage
    float cand[CAP];
    float red[2 * NWARP];
    float tau;
    int   cnt;
    int   done;
};

__device__ __forceinline__ uint32_t s2u(const void* p) {
    return (uint32_t)__cvta_generic_to_shared(p);
}
__device__ __forceinline__ void mbar_init(uint32_t a, uint32_t cnt) {
    asm volatile("mbarrier.init.shared.b64 [%0], %1;" :: "r"(a), "r"(cnt) : "memory");
}
__device__ __forceinline__ void mbar_expect_tx(uint32_t a, uint32_t bytes) {
    asm volatile("mbarrier.arrive.expect_tx.shared.b64 _, [%0], %1;"
                 :: "r"(a), "r"(bytes) : "memory");
}
__device__ __forceinline__ void bulk_g2s(uint32_t dst, const void* src,
                                         uint32_t bytes, uint32_t mbar) {
    asm volatile(
        "cp.async.bulk.shared::cta.global.mbarrier::complete_tx::bytes [%0], [%1], %2, [%3];"
        :: "r"(dst), "l"(src), "r"(bytes), "r"(mbar) : "memory");
}
__device__ __forceinline__ void mbar_wait(uint32_t a, uint32_t parity) {
    uint32_t done;
    asm volatile(
        "{\n\t.reg .pred p;\n\t"
        "mbarrier.try_wait.parity.acquire.cta.shared::cta.b64 p, [%1], %2;\n\t"
        "selp.b32 %0, 1, 0, p;\n\t}"
        : "=r"(done) : "r"(a), "r"(parity) : "memory");
    if (!done) {
        asm volatile(
            "{\n\t.reg .pred P1;\n\t"
            "W_%=:\n\t"
            "mbarrier.try_wait.parity.acquire.cta.shared::cta.b64 P1, [%0], %1, 0x989680;\n\t"
            "@P1 bra.uni D_%=;\n\t"
            "bra.uni W_%=;\n\t"
            "D_%=:\n\t}"
            :: "r"(a), "r"(parity) : "memory");
    }
}

__global__ __launch_bounds__(THREADS, 1)
void sparsemax_persistent(const float* __restrict__ x, float* __restrict__ out, int rows)
{
    extern __shared__ __align__(128) unsigned char smem_raw[];
    Smem* S = reinterpret_cast<Smem*>(smem_raw);

    const int tid  = threadIdx.x;
    const int lane = tid & 31;
    const int wid  = tid >> 5;
    const uint32_t mb0 = s2u(&S->mbar[0]);
    const uint32_t mb1 = s2u(&S->mbar[1]);

    if (tid == 0) { mbar_init(mb0, 1); mbar_init(mb1, 1); }
    __syncthreads();

    const long long stride = gridDim.x;
    long long j0 = blockIdx.x;
    int phase0 = 0, phase1 = 0;

    // prologue: kick off first row into buf[0]
    if (tid == 0 && j0 < rows) {
        mbar_expect_tx(mb0, ROW_BYTES);
        bulk_g2s(s2u(S->buf[0]), (const void*)(x + j0 * COLS), ROW_BYTES, mb0);
    }

    int stage = 0;
    for (long long j = j0; j < rows; j += stride) {
        const int other = stage ^ 1;
        const long long jn = j + stride;

        // issue the NEXT row's bulk copy into the other buffer (its readers
        // finished at the trailing __syncthreads of the previous iteration)
        if (tid == 0 && jn < rows) {
            uint32_t mbo = other ? mb1 : mb0;
            mbar_expect_tx(mbo, ROW_BYTES);
            bulk_g2s(s2u(S->buf[other]), (const void*)(x + jn * COLS), ROW_BYTES, mbo);
        }

        // wait for current row's data
        if (stage == 0) { mbar_wait(mb0, phase0); phase0 ^= 1; }
        else            { mbar_wait(mb1, phase1); phase1 ^= 1; }

        const float4* b4 = reinterpret_cast<const float4*>(S->buf[stage]);

        // ---- pass A: row max ----
        float m = -3.402823466e38f;
#pragma unroll
        for (int i = 0; i < 4; ++i) {
            float4 v = b4[tid + i * THREADS];
            m = fmaxf(m, fmaxf(fmaxf(v.x, v.y), fmaxf(v.z, v.w)));
        }
#pragma unroll
        for (int o = 16; o > 0; o >>= 1) m = fmaxf(m, __shfl_xor_sync(0xffffffffu, m, o));
        if (lane == 0) S->red[wid] = m;
        __syncthreads();
        if (wid == 0) {
            float t = (lane < NWARP) ? S->red[lane] : -3.402823466e38f;
#pragma unroll
            for (int o = 8; o > 0; o >>= 1) t = fmaxf(t, __shfl_xor_sync(0xffffffffu, t, o));
            if (lane == 0) { S->red[0] = t; S->cnt = 0; }
        }
        __syncthreads();
        const float rmax   = S->red[0];
        const float thresh = rmax - 1.0f;   // tau >= thresh

        // ---- gather candidates > thresh ----
#pragma unroll
        for (int i = 0; i < 4; ++i) {
            float4 v = b4[tid + i * THREADS];
            const float e[4] = {v.x, v.y, v.z, v.w};
#pragma unroll
            for (int k = 0; k < 4; ++k) {
                if (e[k] > thresh) {
                    int p = atomicAdd(&S->cnt, 1);
                    if (p < CAP) S->cand[p] = e[k];
                }
            }
        }
        __syncthreads();
        const int cnt = S->cnt;

        float tau;
        if (cnt <= CAP) {
            // ---- exact Newton/Michelot on tiny candidate set (warp 0) ----
            if (wid == 0) {
                float t0 = thresh;
                for (int it = 0; it < 64; ++it) {
                    float s = 0.0f, k = 0.0f;
                    for (int i = lane; i < cnt; i += 32) {
                        float c = S->cand[i];
                        if (c > t0) { s += c; k += 1.0f; }
                    }
#pragma unroll
                    for (int o = 16; o > 0; o >>= 1) {
                        s += __shfl_xor_sync(0xffffffffu, s, o);
                        k += __shfl_xor_sync(0xffffffffu, k, o);
                    }
                    if (k < 0.5f) break;          // safety (cannot happen in theory)
                    float nt = (s - 1.0f) / k;
                    if (nt == t0) break;          // exact fixed point
                    t0 = nt;
                }
                if (lane == 0) S->tau = t0;
            }
            __syncthreads();
            tau = S->tau;
        } else {
            // ---- fallback: block-wide Michelot over smem row (not expected) ----
            float t0 = thresh;
            for (int it = 0; it < 64; ++it) {
                float s = 0.0f, k = 0.0f;
#pragma unroll
                for (int i = 0; i < 4; ++i) {
                    float4 v = b4[tid + i * THREADS];
                    const float e[4] = {v.x, v.y, v.z, v.w};
#pragma unroll
                    for (int q = 0; q < 4; ++q)
                        if (e[q] > t0) { s += e[q]; k += 1.0f; }
                }
#pragma unroll
                for (int o = 16; o > 0; o >>= 1) {
                    s += __shfl_xor_sync(0xffffffffu, s, o);
                    k += __shfl_xor_sync(0xffffffffu, k, o);
                }
                if (lane == 0) { S->red[2 * wid] = s; S->red[2 * wid + 1] = k; }
                __syncthreads();
                if (tid == 0) {
                    float Sx = 0.0f, K = 0.0f;
                    for (int w = 0; w < NWARP; ++w) { Sx += S->red[2 * w]; K += S->red[2 * w + 1]; }
                    float nt = (K < 0.5f) ? t0 : (Sx - 1.0f) / K;
                    S->done = (nt == t0) || (K < 0.5f);
                    S->tau  = nt;
                }
                __syncthreads();
                t0 = S->tau;
                if (S->done) break;
            }
            tau = t0;
        }

        // ---- emit output ----
        float4* y4 = reinterpret_cast<float4*>(out + j * COLS);
#pragma unroll
        for (int i = 0; i < 4; ++i) {
            float4 v = b4[tid + i * THREADS];
            float4 r;
            r.x = fmaxf(v.x - tau, 0.0f);
            r.y = fmaxf(v.y - tau, 0.0f);
            r.z = fmaxf(v.z - tau, 0.0f);
            r.w = fmaxf(v.w - tau, 0.0f);
            y4[tid + i * THREADS] = r;
        }
        __syncthreads();   // all smem reads of buf[stage] done before it is refilled
        stage = other;
    }
}

extern "C" void kernel_launch(void* const* d_in, const int* in_sizes, int n_in,
                              void* d_out, int out_size)
{
    const float* x = (const float*)d_in[0];
    float* out     = (float*)d_out;
    const int rows = in_sizes[0] / COLS;
    cudaFuncSetAttribute(sparsemax_persistent,
                         cudaFuncAttributeMaxDynamicSharedMemorySize,
                         (int)sizeof(Smem));
    sparsemax_persistent<<<GRID, THREADS, sizeof(Smem)>>>(x, out, rows);
}